// round 13
// baseline (speedup 1.0000x reference)
#include <cuda_runtime.h>
#include <cuda_bf16.h>
#include <cstdint>

#define D 128
#define MAX_N    150016
#define MAX_OUT  50048
#define MAX_E    500032   // padded +32: masked gather may read a few slots past E
#define SCAN_CHUNK 4096
#define NBLK 148          // persistent blocks: <= SM count, all co-resident

// ---- device scratch (static zero-init; each replay re-zeroes what it dirtied
//      so every kernel_launch call sees the same initial state) ----
__device__ float  g_deg[MAX_N];          // zeroed in gather phase each run
__device__ int    g_cnt[MAX_OUT];        // zeroed in gather phase each run
__device__ int    g_off[MAX_OUT + 1];    // chunk-LOCAL exclusive offsets
__device__ int    g_cursor[MAX_OUT];     // chunk-LOCAL cursors
__device__ int    g_bsum[64];            // per-chunk totals
__device__ int    g_bpre[64];            // exclusive chunk prefix
__device__ unsigned g_barcnt;            // grid barrier counter (self-resetting)
__device__ unsigned g_exit;              // exit counter (self-resetting)
__device__ int2   g_epack[MAX_E];        // (row, coef) packed 8B
__device__ float  g_agg[(size_t)MAX_OUT * D];
__device__ uint2  g_wf_h[8 * 16 * 32];   // W bf16-hi mma fragments [ks][nt][lane]
__device__ uint2  g_wf_l[8 * 16 * 32];   // W bf16-lo fragments

// ---- helpers ----
__device__ __forceinline__ uint16_t f2bf(float f) {
    __nv_bfloat16 h = __float2bfloat16_rn(f);
    return *reinterpret_cast<uint16_t*>(&h);
}
__device__ __forceinline__ float bf2f(uint16_t u) {
    __nv_bfloat16 h = *reinterpret_cast<__nv_bfloat16*>(&u);
    return __bfloat162float(h);
}
__device__ __forceinline__ uint32_t pack2(uint16_t lo, uint16_t hi) {
    return (uint32_t)lo | ((uint32_t)hi << 16);
}

#define MMA_BF16(ac, a, b0, b1)                                              \
    asm volatile(                                                            \
        "mma.sync.aligned.m16n8k16.row.col.f32.bf16.bf16.f32 "               \
        "{%0,%1,%2,%3}, {%4,%5,%6,%7}, {%8,%9}, {%0,%1,%2,%3};"              \
        : "+f"((ac)[0]), "+f"((ac)[1]), "+f"((ac)[2]), "+f"((ac)[3])         \
        : "r"((a)[0]), "r"((a)[1]), "r"((a)[2]), "r"((a)[3]),                \
          "r"(b0), "r"(b1))

#define LDSM_X4(r, addr)                                                     \
    asm volatile(                                                            \
        "ldmatrix.sync.aligned.m8n8.x4.shared.b16 {%0,%1,%2,%3}, [%4];"      \
        : "=r"((r)[0]), "=r"((r)[1]), "=r"((r)[2]), "=r"((r)[3])             \
        : "r"(addr))

// ---------------------------------------------------------------
// software grid barrier: monotonic counter, all NBLK blocks resident
// ---------------------------------------------------------------
__device__ __forceinline__ void gbar(unsigned target) {
    __syncthreads();
    if (threadIdx.x == 0) {
        __threadfence();
        atomicAdd(&g_barcnt, 1u);
        volatile unsigned* p = &g_barcnt;
        while (*p < target) __nanosleep(64);
        __threadfence();
    }
    __syncthreads();
}

// ---------------------------------------------------------------
// W fragment prep
// ---------------------------------------------------------------
__device__ __forceinline__ void wprep_one(const float* __restrict__ Wm, int idx) {
    int lane = idx & 31, nt = (idx >> 5) & 15, ks = idx >> 9;
    int g = lane >> 2, t = lane & 3;
    int n  = nt * 8 + g;
    int k0 = ks * 16 + 2 * t;
    float w00 = Wm[(k0 + 0) * D + n];
    float w01 = Wm[(k0 + 1) * D + n];
    float w10 = Wm[(k0 + 8) * D + n];
    float w11 = Wm[(k0 + 9) * D + n];
    uint16_t h00 = f2bf(w00), h01 = f2bf(w01), h10 = f2bf(w10), h11 = f2bf(w11);
    uint16_t l00 = f2bf(w00 - bf2f(h00)), l01 = f2bf(w01 - bf2f(h01));
    uint16_t l10 = f2bf(w10 - bf2f(h10)), l11 = f2bf(w11 - bf2f(h11));
    g_wf_h[idx] = make_uint2(pack2(h00, h01), pack2(h10, h11));
    g_wf_l[idx] = make_uint2(pack2(l00, l01), pack2(l10, l11));
}

// ---------------------------------------------------------------
// FUSED front kernel: degcnt -> scan -> prefix -> scatter -> gather
// 148 persistent blocks x 1024 threads, 4 grid barriers.
// ---------------------------------------------------------------
__global__ __launch_bounds__(1024) void fused_kernel(
    const int* __restrict__ ei, const float* __restrict__ ew,
    const float* __restrict__ x, const float* __restrict__ Wm,
    int n_edge, int n_tot, int n_out) {
    __shared__ int wsum[32];
    int tid  = threadIdx.x;
    int gtid = blockIdx.x * 1024 + tid;
    const int gsz = NBLK * 1024;

    // ---- W fragment prep (one shot) ----
    if (gtid < 8 * 16 * 32) wprep_one(Wm, gtid);

    // ---- Phase 1: degree accumulation + dest histogram ----
    for (int e = gtid; e < n_edge; e += gsz) {
        int row = ei[e];
        int col = ei[e + n_edge];
        if ((unsigned)row < (unsigned)n_tot) atomicAdd(&g_deg[row], ew[e]);
        if ((unsigned)col < (unsigned)n_out) atomicAdd(&g_cnt[col], 1);
    }
    gbar(1 * NBLK);

    // ---- Phase 2: per-chunk LOCAL exclusive scan (block c = chunk c) ----
    int nchunks = (n_out + SCAN_CHUNK - 1) / SCAN_CHUNK;
    if ((int)blockIdx.x < nchunks) {
        int lane = tid & 31, wid = tid >> 5;
        int base = blockIdx.x * SCAN_CHUNK + tid * 4;
        int v0 = 0, v1 = 0, v2 = 0, v3 = 0;
        if (base + 3 < n_out) {
            int4 v = *(const int4*)&g_cnt[base];
            v0 = v.x; v1 = v.y; v2 = v.z; v3 = v.w;
        } else {
            if (base + 0 < n_out) v0 = g_cnt[base + 0];
            if (base + 1 < n_out) v1 = g_cnt[base + 1];
            if (base + 2 < n_out) v2 = g_cnt[base + 2];
            if (base + 3 < n_out) v3 = g_cnt[base + 3];
        }
        int tin = v0 + v1 + v2 + v3;
        int incl = tin;
        #pragma unroll
        for (int o = 1; o < 32; o <<= 1) {
            int s = __shfl_up_sync(0xffffffffu, incl, o);
            if (lane >= o) incl += s;
        }
        if (lane == 31) wsum[wid] = incl;
        __syncthreads();
        if (wid == 0) {
            int ws = wsum[lane];
            int winc = ws;
            #pragma unroll
            for (int o = 1; o < 32; o <<= 1) {
                int s = __shfl_up_sync(0xffffffffu, winc, o);
                if (lane >= o) winc += s;
            }
            wsum[lane] = winc - ws;
        }
        __syncthreads();
        int texcl = wsum[wid] + incl - tin;
        int e0 = texcl, e1 = e0 + v0, e2 = e1 + v1, e3 = e2 + v2;
        if (base + 0 < n_out) { g_off[base + 0] = e0; g_cursor[base + 0] = e0; }
        if (base + 1 < n_out) { g_off[base + 1] = e1; g_cursor[base + 1] = e1; }
        if (base + 2 < n_out) { g_off[base + 2] = e2; g_cursor[base + 2] = e2; }
        if (base + 3 < n_out) { g_off[base + 3] = e3; g_cursor[base + 3] = e3; }
        if (n_out >= base && n_out <= base + 3) {   // local sentinel at n_out
            int d = n_out - base;
            g_off[n_out] = (d == 0) ? e0 : (d == 1) ? e1 : (d == 2) ? e2 : e3;
        }
        if (tid == 1023) g_bsum[blockIdx.x] = wsum[wid] + incl;  // chunk TOTAL
    }
    gbar(2 * NBLK);

    // ---- Phase 2b: chunk-prefix (block 0, warp 0) ----
    if (blockIdx.x == 0 && tid < 32) {
        int v = (tid < nchunks) ? g_bsum[tid] : 0;
        int ip = v;
        #pragma unroll
        for (int o = 1; o < 32; o <<= 1) {
            int s = __shfl_up_sync(0xffffffffu, ip, o);
            if (tid >= o) ip += s;
        }
        if (tid <= nchunks) g_bpre[tid] = ip - v;
        if (tid == 0 && (n_out % SCAN_CHUNK) == 0) g_off[n_out] = 0;
    }
    gbar(3 * NBLK);

    // ---- Phase 3: CSR placement (coef = w * rsqrt(1+deg)) ----
    for (int e = gtid; e < n_edge; e += gsz) {
        int row = ei[e];
        int col = ei[e + n_edge];
        if ((unsigned)row >= (unsigned)n_tot || (unsigned)col >= (unsigned)n_out)
            continue;
        float c = ew[e] * rsqrtf(1.0f + g_deg[row]);
        int p = atomicAdd(&g_cursor[col], 1) + g_bpre[col >> 12];
        g_epack[p] = make_int2(row, __float_as_int(c));
    }
    gbar(4 * NBLK);

    // ---- Phase 4: warp-per-node gather (fp32, masked 4-wide) +
    //      scratch re-zero for the next replay ----
    for (int i = gtid; i < n_tot; i += gsz) g_deg[i] = 0.0f;
    for (int i = gtid; i < n_out; i += gsz) g_cnt[i] = 0;

    {
        int lane = tid & 31;
        const float4* x4 = (const float4*)x;
        for (int w = gtid >> 5; w < n_out; w += gsz >> 5) {
            int s = g_off[w]     + g_bpre[w >> 12];
            int e = g_off[w + 1] + g_bpre[(w + 1) >> 12];
            float4 acc = make_float4(0.f, 0.f, 0.f, 0.f);
            #pragma unroll 2
            for (int i = s; i < e; i += 4) {
                int2 p0 = g_epack[i];
                int2 p1 = g_epack[i + 1];
                int2 p2 = g_epack[i + 2];
                int2 p3 = g_epack[i + 3];
                float c0 = __int_as_float(p0.y);
                float c1 = (i + 1 < e) ? __int_as_float(p1.y) : 0.f;
                float c2 = (i + 2 < e) ? __int_as_float(p2.y) : 0.f;
                float c3 = (i + 3 < e) ? __int_as_float(p3.y) : 0.f;
                float4 v0 = x4[(size_t)p0.x * 32 + lane];
                float4 v1 = x4[(size_t)p1.x * 32 + lane];
                float4 v2 = x4[(size_t)p2.x * 32 + lane];
                float4 v3 = x4[(size_t)p3.x * 32 + lane];
                acc.x += c0 * v0.x + c1 * v1.x + c2 * v2.x + c3 * v3.x;
                acc.y += c0 * v0.y + c1 * v1.y + c2 * v2.y + c3 * v3.y;
                acc.z += c0 * v0.z + c1 * v1.z + c2 * v2.z + c3 * v3.z;
                acc.w += c0 * v0.w + c1 * v1.w + c2 * v2.w + c3 * v3.w;
            }
            ((float4*)g_agg)[(size_t)w * 32 + lane] = acc;
        }
    }

    // ---- epilogue: reset barrier state for the next graph replay ----
    __syncthreads();
    if (tid == 0) {
        unsigned v = atomicAdd(&g_exit, 1u);
        if (v == NBLK - 1) {
            g_barcnt = 0;
            g_exit = 0;
            __threadfence();
        }
    }
}

// ---------------------------------------------------------------
// K5: tensor-core GEMM  out = relu(agg @ W + b)
//   block = 128 rows x 128 cols, 8 warps (16 rows each)
//   bf16 2-way split: acc = Ah*Wh + Ah*Wl + Al*Wh  (fp32 accum)
//   smem: Ah/Al only (69.6 KB), PADDED to 88 KB to cap residency at
//   2 blocks/SM (3 blocks would evict the W table from L1).
//   W fragments read from global via __ldg: 64 KB table shared by
//   all warps -> L1/L2-resident; occupancy 12.5% -> 25%.
// ---------------------------------------------------------------
#define A_STRIDE 136
#define GEMM_SMEM 90112   // 88 KB: 69632 used + pad (caps 2 blocks/SM)

__global__ __launch_bounds__(256) void mma_gemm_kernel(const float* __restrict__ bias,
                                                       float* __restrict__ out,
                                                       int n_rows) {
    extern __shared__ char smem[];
    uint16_t* Ah = (uint16_t*)smem;                 // 34816 B
    uint16_t* Al = Ah + 128 * A_STRIDE;             // +34816 B

    int tid = threadIdx.x;
    int w = tid >> 5, lane = tid & 31;
    int g = lane >> 2, t = lane & 3;
    int row0 = blockIdx.x * 128;

    // ---- stage A: load fp32 agg, split to bf16 hi/lo in smem ----
    #pragma unroll
    for (int i = 0; i < 16; i++) {
        int idx4 = tid + i * 256;          // 0..4095
        int r  = idx4 >> 5;                // 0..127
        int c4 = idx4 & 31;                // 0..31
        float4 v = make_float4(0.f, 0.f, 0.f, 0.f);
        if (row0 + r < n_rows)
            v = *(const float4*)&g_agg[(size_t)(row0 + r) * D + c4 * 4];
        uint16_t h0 = f2bf(v.x), h1 = f2bf(v.y), h2 = f2bf(v.z), h3 = f2bf(v.w);
        uint16_t l0 = f2bf(v.x - bf2f(h0)), l1 = f2bf(v.y - bf2f(h1));
        uint16_t l2 = f2bf(v.z - bf2f(h2)), l3 = f2bf(v.w - bf2f(h3));
        *(uint2*)&Ah[r * A_STRIDE + c4 * 4] = make_uint2(pack2(h0, h1), pack2(h2, h3));
        *(uint2*)&Al[r * A_STRIDE + c4 * 4] = make_uint2(pack2(l0, l1), pack2(l2, l3));
    }
    __syncthreads();

    // ---- main mma loops ----
    float acc[16][4];
    #pragma unroll
    for (int nt = 0; nt < 16; nt++)
        #pragma unroll
        for (int j = 0; j < 4; j++) acc[nt][j] = 0.f;

    int lrow = w * 16 + (lane & 15);
    int lch  = (lane >> 4) & 1;

    for (int ks = 0; ks < 8; ks++) {
        uint32_t ah[4], al[4];
        uint32_t a_h = (uint32_t)__cvta_generic_to_shared(
            &Ah[lrow * A_STRIDE + ks * 16 + lch * 8]);
        uint32_t a_l = (uint32_t)__cvta_generic_to_shared(
            &Al[lrow * A_STRIDE + ks * 16 + lch * 8]);
        LDSM_X4(ah, a_h);
        LDSM_X4(al, a_l);
        const uint2* wh = &g_wf_h[ks * 16 * 32 + lane];
        const uint2* wl = &g_wf_l[ks * 16 * 32 + lane];
        #pragma unroll
        for (int nt = 0; nt < 16; nt++) {
            uint2 bh = __ldg(wh + nt * 32);
            uint2 bl = __ldg(wl + nt * 32);
            MMA_BF16(acc[nt], ah, bh.x, bh.y);
            MMA_BF16(acc[nt], ah, bl.x, bl.y);
            MMA_BF16(acc[nt], al, bh.x, bh.y);
        }
    }

    // ---- epilogue: bias + relu + store ----
    int r_lo = row0 + w * 16 + g;
    int r_hi = r_lo + 8;
    #pragma unroll
    for (int nt = 0; nt < 16; nt++) {
        int col = nt * 8 + 2 * t;
        float2 bv = *(const float2*)&bias[col];
        if (r_lo < n_rows) {
            float2 o;
            o.x = fmaxf(acc[nt][0] + bv.x, 0.f);
            o.y = fmaxf(acc[nt][1] + bv.y, 0.f);
            *(float2*)&out[(size_t)r_lo * D + col] = o;
        }
        if (r_hi < n_rows) {
            float2 o;
            o.x = fmaxf(acc[nt][2] + bv.x, 0.f);
            o.y = fmaxf(acc[nt][3] + bv.y, 0.f);
            *(float2*)&out[(size_t)r_hi * D + col] = o;
        }
    }
}

// ---------------------------------------------------------------
extern "C" void kernel_launch(void* const* d_in, const int* in_sizes, int n_in,
                              void* d_out, int out_size) {
    const float* x  = (const float*)d_in[0];   // [n_src, 128]
    const int*   ei = (const int*)d_in[1];     // [2, n_edge] int32
    const float* ew = (const float*)d_in[2];   // [n_edge]
    const float* Wm = (const float*)d_in[3];   // [128, 128]
    const float* b  = (const float*)d_in[4];   // [128]
    float* out = (float*)d_out;                // [n_out, 128]

    int n_src  = in_sizes[0] / D;
    int n_edge = in_sizes[2];
    int n_out  = out_size / D;
    int n_tot  = n_src + n_out;

    cudaFuncSetAttribute(mma_gemm_kernel,
                         cudaFuncAttributeMaxDynamicSharedMemorySize, GEMM_SMEM);

    fused_kernel<<<NBLK, 1024>>>(ei, ew, x, Wm, n_edge, n_tot, n_out);
    mma_gemm_kernel<<<(n_out + 127) / 128, 256, GEMM_SMEM>>>(b, out, n_out);
}

// round 14
// speedup vs baseline: 1.1342x; 1.1342x over previous
#include <cuda_runtime.h>
#include <cuda_bf16.h>
#include <cstdint>

#define D 128
#define MAX_N    150016
#define MAX_OUT  50048
#define MAX_E    500032   // padded +32: masked gather may read a few slots past E
#define SCAN_CHUNK 4096
#define NBLK 148          // persistent blocks: <= SM count, all co-resident

// ---- device scratch (static zero-init; each replay re-zeroes what it dirtied
//      so every kernel_launch call sees the same initial state) ----
__device__ float  g_deg[MAX_N];          // zeroed in gather phase each run
__device__ int    g_cnt[MAX_OUT];        // zeroed in gather phase each run
__device__ int    g_off[MAX_OUT + 1];    // chunk-LOCAL exclusive offsets
__device__ int    g_cursor[MAX_OUT];     // chunk-LOCAL cursors
__device__ int    g_bsum[64];            // per-chunk totals
__device__ int    g_bpre[64];            // exclusive chunk prefix
__device__ unsigned g_barcnt;            // grid barrier counter (self-resetting)
__device__ unsigned g_exit;              // exit counter (self-resetting)
__device__ int2   g_epack[MAX_E];        // (row, coef) packed 8B
__device__ float  g_agg[(size_t)MAX_OUT * D];
__device__ uint2  g_wf_h[8 * 16 * 32];   // W bf16-hi mma fragments [ks][nt][lane]
__device__ uint2  g_wf_l[8 * 16 * 32];   // W bf16-lo fragments

// ---- helpers ----
__device__ __forceinline__ uint16_t f2bf(float f) {
    __nv_bfloat16 h = __float2bfloat16_rn(f);
    return *reinterpret_cast<uint16_t*>(&h);
}
__device__ __forceinline__ float bf2f(uint16_t u) {
    __nv_bfloat16 h = *reinterpret_cast<__nv_bfloat16*>(&u);
    return __bfloat162float(h);
}
__device__ __forceinline__ uint32_t pack2(uint16_t lo, uint16_t hi) {
    return (uint32_t)lo | ((uint32_t)hi << 16);
}

#define MMA_BF16(ac, a, b0, b1)                                              \
    asm volatile(                                                            \
        "mma.sync.aligned.m16n8k16.row.col.f32.bf16.bf16.f32 "               \
        "{%0,%1,%2,%3}, {%4,%5,%6,%7}, {%8,%9}, {%0,%1,%2,%3};"              \
        : "+f"((ac)[0]), "+f"((ac)[1]), "+f"((ac)[2]), "+f"((ac)[3])         \
        : "r"((a)[0]), "r"((a)[1]), "r"((a)[2]), "r"((a)[3]),                \
          "r"(b0), "r"(b1))

#define LDSM_X4(r, addr)                                                     \
    asm volatile(                                                            \
        "ldmatrix.sync.aligned.m8n8.x4.shared.b16 {%0,%1,%2,%3}, [%4];"      \
        : "=r"((r)[0]), "=r"((r)[1]), "=r"((r)[2]), "=r"((r)[3])             \
        : "r"(addr))

// ---------------------------------------------------------------
// software grid barrier: monotonic counter, all NBLK blocks resident
// ---------------------------------------------------------------
__device__ __forceinline__ void gbar(unsigned target) {
    __syncthreads();
    if (threadIdx.x == 0) {
        __threadfence();
        atomicAdd(&g_barcnt, 1u);
        volatile unsigned* p = &g_barcnt;
        while (*p < target) __nanosleep(64);
        __threadfence();
    }
    __syncthreads();
}

// ---------------------------------------------------------------
// W fragment prep
// ---------------------------------------------------------------
__device__ __forceinline__ void wprep_one(const float* __restrict__ Wm, int idx) {
    int lane = idx & 31, nt = (idx >> 5) & 15, ks = idx >> 9;
    int g = lane >> 2, t = lane & 3;
    int n  = nt * 8 + g;
    int k0 = ks * 16 + 2 * t;
    float w00 = Wm[(k0 + 0) * D + n];
    float w01 = Wm[(k0 + 1) * D + n];
    float w10 = Wm[(k0 + 8) * D + n];
    float w11 = Wm[(k0 + 9) * D + n];
    uint16_t h00 = f2bf(w00), h01 = f2bf(w01), h10 = f2bf(w10), h11 = f2bf(w11);
    uint16_t l00 = f2bf(w00 - bf2f(h00)), l01 = f2bf(w01 - bf2f(h01));
    uint16_t l10 = f2bf(w10 - bf2f(h10)), l11 = f2bf(w11 - bf2f(h11));
    g_wf_h[idx] = make_uint2(pack2(h00, h01), pack2(h10, h11));
    g_wf_l[idx] = make_uint2(pack2(l00, l01), pack2(l10, l11));
}

// ---------------------------------------------------------------
// FUSED front kernel: degcnt -> scan -> prefix -> scatter -> gather
// 148 persistent blocks x 1024 threads, 4 grid barriers.
// ---------------------------------------------------------------
__global__ __launch_bounds__(1024) void fused_kernel(
    const int* __restrict__ ei, const float* __restrict__ ew,
    const float* __restrict__ x, const float* __restrict__ Wm,
    int n_edge, int n_tot, int n_out) {
    __shared__ int wsum[32];
    int tid  = threadIdx.x;
    int gtid = blockIdx.x * 1024 + tid;
    const int gsz = NBLK * 1024;

    // ---- W fragment prep (one shot) ----
    if (gtid < 8 * 16 * 32) wprep_one(Wm, gtid);

    // ---- Phase 1: degree accumulation + dest histogram ----
    for (int e = gtid; e < n_edge; e += gsz) {
        int row = ei[e];
        int col = ei[e + n_edge];
        if ((unsigned)row < (unsigned)n_tot) atomicAdd(&g_deg[row], ew[e]);
        if ((unsigned)col < (unsigned)n_out) atomicAdd(&g_cnt[col], 1);
    }
    gbar(1 * NBLK);

    // ---- Phase 2: per-chunk LOCAL exclusive scan (block c = chunk c) ----
    int nchunks = (n_out + SCAN_CHUNK - 1) / SCAN_CHUNK;
    if ((int)blockIdx.x < nchunks) {
        int lane = tid & 31, wid = tid >> 5;
        int base = blockIdx.x * SCAN_CHUNK + tid * 4;
        int v0 = 0, v1 = 0, v2 = 0, v3 = 0;
        if (base + 3 < n_out) {
            int4 v = *(const int4*)&g_cnt[base];
            v0 = v.x; v1 = v.y; v2 = v.z; v3 = v.w;
        } else {
            if (base + 0 < n_out) v0 = g_cnt[base + 0];
            if (base + 1 < n_out) v1 = g_cnt[base + 1];
            if (base + 2 < n_out) v2 = g_cnt[base + 2];
            if (base + 3 < n_out) v3 = g_cnt[base + 3];
        }
        int tin = v0 + v1 + v2 + v3;
        int incl = tin;
        #pragma unroll
        for (int o = 1; o < 32; o <<= 1) {
            int s = __shfl_up_sync(0xffffffffu, incl, o);
            if (lane >= o) incl += s;
        }
        if (lane == 31) wsum[wid] = incl;
        __syncthreads();
        if (wid == 0) {
            int ws = wsum[lane];
            int winc = ws;
            #pragma unroll
            for (int o = 1; o < 32; o <<= 1) {
                int s = __shfl_up_sync(0xffffffffu, winc, o);
                if (lane >= o) winc += s;
            }
            wsum[lane] = winc - ws;
        }
        __syncthreads();
        int texcl = wsum[wid] + incl - tin;
        int e0 = texcl, e1 = e0 + v0, e2 = e1 + v1, e3 = e2 + v2;
        if (base + 0 < n_out) { g_off[base + 0] = e0; g_cursor[base + 0] = e0; }
        if (base + 1 < n_out) { g_off[base + 1] = e1; g_cursor[base + 1] = e1; }
        if (base + 2 < n_out) { g_off[base + 2] = e2; g_cursor[base + 2] = e2; }
        if (base + 3 < n_out) { g_off[base + 3] = e3; g_cursor[base + 3] = e3; }
        if (n_out >= base && n_out <= base + 3) {   // local sentinel at n_out
            int d = n_out - base;
            g_off[n_out] = (d == 0) ? e0 : (d == 1) ? e1 : (d == 2) ? e2 : e3;
        }
        if (tid == 1023) g_bsum[blockIdx.x] = wsum[wid] + incl;  // chunk TOTAL
    }
    gbar(2 * NBLK);

    // ---- Phase 2b: chunk-prefix (block 0, warp 0) ----
    if (blockIdx.x == 0 && tid < 32) {
        int v = (tid < nchunks) ? g_bsum[tid] : 0;
        int ip = v;
        #pragma unroll
        for (int o = 1; o < 32; o <<= 1) {
            int s = __shfl_up_sync(0xffffffffu, ip, o);
            if (tid >= o) ip += s;
        }
        if (tid <= nchunks) g_bpre[tid] = ip - v;
        if (tid == 0 && (n_out % SCAN_CHUNK) == 0) g_off[n_out] = 0;
    }
    gbar(3 * NBLK);

    // ---- Phase 3: CSR placement (coef = w * rsqrt(1+deg)) ----
    for (int e = gtid; e < n_edge; e += gsz) {
        int row = ei[e];
        int col = ei[e + n_edge];
        if ((unsigned)row >= (unsigned)n_tot || (unsigned)col >= (unsigned)n_out)
            continue;
        float c = ew[e] * rsqrtf(1.0f + g_deg[row]);
        int p = atomicAdd(&g_cursor[col], 1) + g_bpre[col >> 12];
        g_epack[p] = make_int2(row, __float_as_int(c));
    }
    gbar(4 * NBLK);

    // ---- Phase 4: warp-per-node gather (fp32, masked 4-wide) +
    //      scratch re-zero for the next replay ----
    for (int i = gtid; i < n_tot; i += gsz) g_deg[i] = 0.0f;
    for (int i = gtid; i < n_out; i += gsz) g_cnt[i] = 0;

    {
        int lane = tid & 31;
        const float4* x4 = (const float4*)x;
        for (int w = gtid >> 5; w < n_out; w += gsz >> 5) {
            int s = g_off[w]     + g_bpre[w >> 12];
            int e = g_off[w + 1] + g_bpre[(w + 1) >> 12];
            float4 acc = make_float4(0.f, 0.f, 0.f, 0.f);
            #pragma unroll 2
            for (int i = s; i < e; i += 4) {
                int2 p0 = g_epack[i];
                int2 p1 = g_epack[i + 1];
                int2 p2 = g_epack[i + 2];
                int2 p3 = g_epack[i + 3];
                float c0 = __int_as_float(p0.y);
                float c1 = (i + 1 < e) ? __int_as_float(p1.y) : 0.f;
                float c2 = (i + 2 < e) ? __int_as_float(p2.y) : 0.f;
                float c3 = (i + 3 < e) ? __int_as_float(p3.y) : 0.f;
                float4 v0 = x4[(size_t)p0.x * 32 + lane];
                float4 v1 = x4[(size_t)p1.x * 32 + lane];
                float4 v2 = x4[(size_t)p2.x * 32 + lane];
                float4 v3 = x4[(size_t)p3.x * 32 + lane];
                acc.x += c0 * v0.x + c1 * v1.x + c2 * v2.x + c3 * v3.x;
                acc.y += c0 * v0.y + c1 * v1.y + c2 * v2.y + c3 * v3.y;
                acc.z += c0 * v0.z + c1 * v1.z + c2 * v2.z + c3 * v3.z;
                acc.w += c0 * v0.w + c1 * v1.w + c2 * v2.w + c3 * v3.w;
            }
            ((float4*)g_agg)[(size_t)w * 32 + lane] = acc;
        }
    }

    // ---- epilogue: reset barrier state for the next graph replay ----
    __syncthreads();
    if (tid == 0) {
        unsigned v = atomicAdd(&g_exit, 1u);
        if (v == NBLK - 1) {
            g_barcnt = 0;
            g_exit = 0;
            __threadfence();
        }
    }
}

// ---------------------------------------------------------------
// K5: tensor-core GEMM  out = relu(agg @ W + b)
//   block = 64 rows x 128 cols, 8 warps: 4 row-groups x 2 col-halves
//   (each warp: 16 rows x 64 cols, acc[8][4])
//   bf16 2-way split: acc = Ah*Wh + Ah*Wl + Al*Wh  (fp32 accum)
//   smem: Ah/Al (34.8 KB) + staged W fragments (64 KB) = 98 KB
//   -> 2 blocks/SM (occupancy 25%), W stays in smem (R13 rule).
// ---------------------------------------------------------------
#define A_STRIDE 136
#define GEMM_ROWS 64
#define GEMM_SMEM (2 * GEMM_ROWS * A_STRIDE * 2 + 2 * 4096 * 8)  // 100352

__global__ __launch_bounds__(256) void mma_gemm_kernel(const float* __restrict__ bias,
                                                       float* __restrict__ out,
                                                       int n_rows) {
    extern __shared__ char smem[];
    uint16_t* Ah = (uint16_t*)smem;                              // 17408 B
    uint16_t* Al = Ah + GEMM_ROWS * A_STRIDE;                    // +17408 B
    uint2*    Wfh = (uint2*)(smem + 2 * GEMM_ROWS * A_STRIDE * 2); // +32768 B
    uint2*    Wfl = Wfh + 4096;                                  // +32768 B

    int tid = threadIdx.x;
    int w = tid >> 5, lane = tid & 31;
    int g = lane >> 2, t = lane & 3;
    int wr = w & 3;        // row group (16 rows each)
    int wc = w >> 2;       // col half  (64 cols each)
    int row0 = blockIdx.x * GEMM_ROWS;

    // ---- stage W fragments ----
    #pragma unroll
    for (int i = tid; i < 4096; i += 256) {
        Wfh[i] = g_wf_h[i];
        Wfl[i] = g_wf_l[i];
    }

    // ---- stage A: load fp32 agg, split to bf16 hi/lo in smem ----
    #pragma unroll
    for (int i = 0; i < 8; i++) {
        int idx4 = tid + i * 256;          // 0..2047
        int r  = idx4 >> 5;                // 0..63
        int c4 = idx4 & 31;                // 0..31
        float4 v = make_float4(0.f, 0.f, 0.f, 0.f);
        if (row0 + r < n_rows)
            v = *(const float4*)&g_agg[(size_t)(row0 + r) * D + c4 * 4];
        uint16_t h0 = f2bf(v.x), h1 = f2bf(v.y), h2 = f2bf(v.z), h3 = f2bf(v.w);
        uint16_t l0 = f2bf(v.x - bf2f(h0)), l1 = f2bf(v.y - bf2f(h1));
        uint16_t l2 = f2bf(v.z - bf2f(h2)), l3 = f2bf(v.w - bf2f(h3));
        *(uint2*)&Ah[r * A_STRIDE + c4 * 4] = make_uint2(pack2(h0, h1), pack2(h2, h3));
        *(uint2*)&Al[r * A_STRIDE + c4 * 4] = make_uint2(pack2(l0, l1), pack2(l2, l3));
    }
    __syncthreads();

    // ---- main mma loops ----
    float acc[8][4];
    #pragma unroll
    for (int nt = 0; nt < 8; nt++)
        #pragma unroll
        for (int j = 0; j < 4; j++) acc[nt][j] = 0.f;

    int lrow = wr * 16 + (lane & 15);
    int lch  = (lane >> 4) & 1;

    for (int ks = 0; ks < 8; ks++) {
        uint32_t ah[4], al[4];
        uint32_t a_h = (uint32_t)__cvta_generic_to_shared(
            &Ah[lrow * A_STRIDE + ks * 16 + lch * 8]);
        uint32_t a_l = (uint32_t)__cvta_generic_to_shared(
            &Al[lrow * A_STRIDE + ks * 16 + lch * 8]);
        LDSM_X4(ah, a_h);
        LDSM_X4(al, a_l);
        #pragma unroll
        for (int nt = 0; nt < 8; nt++) {
            int ntg = wc * 8 + nt;
            uint2 bh = Wfh[(ks * 16 + ntg) * 32 + lane];
            uint2 bl = Wfl[(ks * 16 + ntg) * 32 + lane];
            MMA_BF16(acc[nt], ah, bh.x, bh.y);
            MMA_BF16(acc[nt], ah, bl.x, bl.y);
            MMA_BF16(acc[nt], al, bh.x, bh.y);
        }
    }

    // ---- epilogue: bias + relu + store ----
    int r_lo = row0 + wr * 16 + g;
    int r_hi = r_lo + 8;
    #pragma unroll
    for (int nt = 0; nt < 8; nt++) {
        int col = wc * 64 + nt * 8 + 2 * t;
        float2 bv = *(const float2*)&bias[col];
        if (r_lo < n_rows) {
            float2 o;
            o.x = fmaxf(acc[nt][0] + bv.x, 0.f);
            o.y = fmaxf(acc[nt][1] + bv.y, 0.f);
            *(float2*)&out[(size_t)r_lo * D + col] = o;
        }
        if (r_hi < n_rows) {
            float2 o;
            o.x = fmaxf(acc[nt][2] + bv.x, 0.f);
            o.y = fmaxf(acc[nt][3] + bv.y, 0.f);
            *(float2*)&out[(size_t)r_hi * D + col] = o;
        }
    }
}

// ---------------------------------------------------------------
extern "C" void kernel_launch(void* const* d_in, const int* in_sizes, int n_in,
                              void* d_out, int out_size) {
    const float* x  = (const float*)d_in[0];   // [n_src, 128]
    const int*   ei = (const int*)d_in[1];     // [2, n_edge] int32
    const float* ew = (const float*)d_in[2];   // [n_edge]
    const float* Wm = (const float*)d_in[3];   // [128, 128]
    const float* b  = (const float*)d_in[4];   // [128]
    float* out = (float*)d_out;                // [n_out, 128]

    int n_src  = in_sizes[0] / D;
    int n_edge = in_sizes[2];
    int n_out  = out_size / D;
    int n_tot  = n_src + n_out;

    cudaFuncSetAttribute(mma_gemm_kernel,
                         cudaFuncAttributeMaxDynamicSharedMemorySize, GEMM_SMEM);

    fused_kernel<<<NBLK, 1024>>>(ei, ew, x, Wm, n_edge, n_tot, n_out);
    mma_gemm_kernel<<<(n_out + GEMM_ROWS - 1) / GEMM_ROWS, 256, GEMM_SMEM>>>(b, out, n_out);
}

// round 15
// speedup vs baseline: 1.1640x; 1.0263x over previous
#include <cuda_runtime.h>
#include <cuda_fp16.h>
#include <cstdint>

#define D 128
#define MAX_N    150016
#define MAX_OUT  50048
#define MAX_E    500032   // padded +32: masked gather may read a few slots past E
#define SCAN_CHUNK 4096

// ---- device scratch (static zero-init; each replay re-zeroes what it dirtied
//      so every kernel_launch call sees the same initial state) ----
__device__ float  g_deg[MAX_N];          // zeroed by gather tail each run
__device__ int    g_cnt[MAX_OUT];        // zeroed by gather tail each run
__device__ int    g_off[MAX_OUT + 1];    // chunk-LOCAL exclusive offsets
__device__ int    g_cursor[MAX_OUT];     // chunk-LOCAL cursors
__device__ int    g_bsum[64];            // per-chunk totals
__device__ int    g_bpre[64];            // exclusive chunk prefix
__device__ int    g_done;                // scanA completion counter (self-resetting)
__device__ int2   g_epack[MAX_E];        // (row, coef) packed 8B
__device__ float  g_agg[(size_t)MAX_OUT * D];
__device__ uint2  g_wf[8 * 16 * 32];     // W fp16 mma fragments [ks][nt][lane]

// ---- helpers ----
__device__ __forceinline__ uint16_t f2h(float f) {
    __half h = __float2half_rn(f);
    return *reinterpret_cast<uint16_t*>(&h);
}
__device__ __forceinline__ uint32_t pack2(uint16_t lo, uint16_t hi) {
    return (uint32_t)lo | ((uint32_t)hi << 16);
}

#define MMA_F16(ac, a, b0, b1)                                               \
    asm volatile(                                                            \
        "mma.sync.aligned.m16n8k16.row.col.f32.f16.f16.f32 "                 \
        "{%0,%1,%2,%3}, {%4,%5,%6,%7}, {%8,%9}, {%0,%1,%2,%3};"              \
        : "+f"((ac)[0]), "+f"((ac)[1]), "+f"((ac)[2]), "+f"((ac)[3])         \
        : "r"((a)[0]), "r"((a)[1]), "r"((a)[2]), "r"((a)[3]),                \
          "r"(b0), "r"(b1))

#define LDSM_X4(r, addr)                                                     \
    asm volatile(                                                            \
        "ldmatrix.sync.aligned.m8n8.x4.shared.b16 {%0,%1,%2,%3}, [%4];"      \
        : "=r"((r)[0]), "=r"((r)[1]), "=r"((r)[2]), "=r"((r)[3])             \
        : "r"(addr))

// ---------------------------------------------------------------
// W fragment prep (fp16, folded into degcnt_kernel)
// frag[ks][nt][lane]: b0b1 = W[ks*16+2t +{0,1}][nt*8+g]
//                     b2b3 = W[ks*16+2t+8 +{0,1}][nt*8+g]
// ---------------------------------------------------------------
__device__ __forceinline__ void wprep_one(const float* __restrict__ Wm, int idx) {
    int lane = idx & 31, nt = (idx >> 5) & 15, ks = idx >> 9;
    int g = lane >> 2, t = lane & 3;
    int n  = nt * 8 + g;
    int k0 = ks * 16 + 2 * t;
    uint16_t h00 = f2h(Wm[(k0 + 0) * D + n]);
    uint16_t h01 = f2h(Wm[(k0 + 1) * D + n]);
    uint16_t h10 = f2h(Wm[(k0 + 8) * D + n]);
    uint16_t h11 = f2h(Wm[(k0 + 9) * D + n]);
    g_wf[idx] = make_uint2(pack2(h00, h01), pack2(h10, h11));
}

// ---------------------------------------------------------------
// K1: degree accumulation (into ZEROED deg; self-loop +1 folded into
//     scatter's rsqrt(1+deg)) + dest histogram + W fragment prep.
// ---------------------------------------------------------------
__global__ void degcnt_kernel(const int* __restrict__ ei,
                              const float* __restrict__ ew,
                              const float* __restrict__ Wm, int n_edge,
                              int n_tot, int n_out) {
    int e = blockIdx.x * blockDim.x + threadIdx.x;
    if (e < 8 * 16 * 32) wprep_one(Wm, e);
    if (e >= n_edge) return;
    int row = ei[e];
    int col = ei[e + n_edge];
    if ((unsigned)row < (unsigned)n_tot) atomicAdd(&g_deg[row], ew[e]);
    if ((unsigned)col < (unsigned)n_out) atomicAdd(&g_cnt[col], 1);
}

// ---------------------------------------------------------------
// K2: per-chunk LOCAL exclusive scan + fused chunk-prefix
//     (last finishing block computes g_bpre, resets g_done)
// ---------------------------------------------------------------
__global__ __launch_bounds__(1024) void scanA_kernel(int n, int nblk) {
    __shared__ int wsum[32];
    __shared__ int is_last;
    int t = threadIdx.x, lane = t & 31, wid = t >> 5;
    int base = blockIdx.x * SCAN_CHUNK + t * 4;
    int v0 = 0, v1 = 0, v2 = 0, v3 = 0;
    if (base + 3 < n) {
        int4 v = *(const int4*)&g_cnt[base];
        v0 = v.x; v1 = v.y; v2 = v.z; v3 = v.w;
    } else {
        if (base + 0 < n) v0 = g_cnt[base + 0];
        if (base + 1 < n) v1 = g_cnt[base + 1];
        if (base + 2 < n) v2 = g_cnt[base + 2];
        if (base + 3 < n) v3 = g_cnt[base + 3];
    }
    int tin = v0 + v1 + v2 + v3;
    int incl = tin;
    #pragma unroll
    for (int o = 1; o < 32; o <<= 1) {
        int s = __shfl_up_sync(0xffffffffu, incl, o);
        if (lane >= o) incl += s;
    }
    if (lane == 31) wsum[wid] = incl;
    __syncthreads();
    if (wid == 0) {
        int ws = wsum[lane];
        int winc = ws;
        #pragma unroll
        for (int o = 1; o < 32; o <<= 1) {
            int s = __shfl_up_sync(0xffffffffu, winc, o);
            if (lane >= o) winc += s;
        }
        wsum[lane] = winc - ws;
    }
    __syncthreads();
    int texcl = wsum[wid] + incl - tin;
    int e0 = texcl, e1 = e0 + v0, e2 = e1 + v1, e3 = e2 + v2;
    if (base + 0 < n) { g_off[base + 0] = e0; g_cursor[base + 0] = e0; }
    if (base + 1 < n) { g_off[base + 1] = e1; g_cursor[base + 1] = e1; }
    if (base + 2 < n) { g_off[base + 2] = e2; g_cursor[base + 2] = e2; }
    if (base + 3 < n) { g_off[base + 3] = e3; g_cursor[base + 3] = e3; }
    if (n >= base && n <= base + 3) {          // local sentinel at n
        int d = n - base;
        g_off[n] = (d == 0) ? e0 : (d == 1) ? e1 : (d == 2) ? e2 : e3;
    }
    if (t == 1023) g_bsum[blockIdx.x] = wsum[wid] + incl;   // chunk TOTAL

    // ---- fused chunk-prefix: last block to finish computes g_bpre ----
    __syncthreads();
    if (t == 0) {
        __threadfence();
        int old = atomicAdd(&g_done, 1);
        is_last = (old == nblk - 1);
    }
    __syncthreads();
    if (is_last && t < 32) {
        int v = (t < nblk) ? g_bsum[t] : 0;
        int ip = v;
        #pragma unroll
        for (int o = 1; o < 32; o <<= 1) {
            int s = __shfl_up_sync(0xffffffffu, ip, o);
            if (t >= o) ip += s;
        }
        if (t <= nblk) g_bpre[t] = ip - v;
        if (t == 0) {
            g_done = 0;                            // reset for next replay
            if ((n % SCAN_CHUNK) == 0) g_off[n] = 0;  // boundary sentinel
        }
    }
}

// ---------------------------------------------------------------
// K3: CSR placement (1 edge/thread), packed 8B store
//     coef = w_e * rsqrt(1 + deg[row]);  slot = local cursor + prefix
// ---------------------------------------------------------------
__global__ void scatter_kernel(const int* __restrict__ ei,
                               const float* __restrict__ ew, int n_edge,
                               int n_tot, int n_out) {
    int e = blockIdx.x * blockDim.x + threadIdx.x;
    if (e >= n_edge) return;
    int row = ei[e];
    int col = ei[e + n_edge];
    if ((unsigned)row >= (unsigned)n_tot || (unsigned)col >= (unsigned)n_out)
        return;
    float c = ew[e] * rsqrtf(1.0f + g_deg[row]);
    int p = atomicAdd(&g_cursor[col], 1) + g_bpre[col >> 12];
    g_epack[p] = make_int2(row, __float_as_int(c));
}

// ---------------------------------------------------------------
// K4: warp-per-node gather (fp32, masked 4-wide, no scalar tail) +
//     scratch re-zero for the next replay
// ---------------------------------------------------------------
__global__ void gather_kernel(const float* __restrict__ x, int n_out, int n_tot) {
    int gtid = blockIdx.x * blockDim.x + threadIdx.x;
    if (gtid < n_tot) g_deg[gtid] = 0.0f;
    if (gtid < n_out) g_cnt[gtid] = 0;

    int w = gtid >> 5;
    int lane = threadIdx.x & 31;
    if (w >= n_out) return;
    int s = g_off[w]     + g_bpre[w >> 12];
    int e = g_off[w + 1] + g_bpre[(w + 1) >> 12];
    const float4* x4 = (const float4*)x;
    float4 acc = make_float4(0.f, 0.f, 0.f, 0.f);
    #pragma unroll 2
    for (int i = s; i < e; i += 4) {
        int2 p0 = g_epack[i];
        int2 p1 = g_epack[i + 1];
        int2 p2 = g_epack[i + 2];
        int2 p3 = g_epack[i + 3];
        float c0 = __int_as_float(p0.y);
        float c1 = (i + 1 < e) ? __int_as_float(p1.y) : 0.f;
        float c2 = (i + 2 < e) ? __int_as_float(p2.y) : 0.f;
        float c3 = (i + 3 < e) ? __int_as_float(p3.y) : 0.f;
        float4 v0 = x4[(size_t)p0.x * 32 + lane];
        float4 v1 = x4[(size_t)p1.x * 32 + lane];
        float4 v2 = x4[(size_t)p2.x * 32 + lane];
        float4 v3 = x4[(size_t)p3.x * 32 + lane];
        acc.x += c0 * v0.x + c1 * v1.x + c2 * v2.x + c3 * v3.x;
        acc.y += c0 * v0.y + c1 * v1.y + c2 * v2.y + c3 * v3.y;
        acc.z += c0 * v0.z + c1 * v1.z + c2 * v2.z + c3 * v3.z;
        acc.w += c0 * v0.w + c1 * v1.w + c2 * v2.w + c3 * v3.w;
    }
    ((float4*)g_agg)[(size_t)w * 32 + lane] = acc;
}

// ---------------------------------------------------------------
// K5: tensor-core GEMM  out = relu(agg @ W + b), SINGLE fp16 MMA
//   (precision: two fp16 roundings ~3e-4 rel, calibrated by R11's
//    measured 2.08e-4 for one rounding; threshold 1e-3)
//   tile = 128 rows x 128 cols, 8 warps: 4 row-groups (32 rows) x
//   2 col-halves (64 cols). acc[2][8][4] = 64 regs.
//   smem: A fp16 (34.8 KB) + W fragments (32 KB) = 66 KB
//   -> 3 blocks/SM, grid 391 <= 444 -> single wave, no tail.
// ---------------------------------------------------------------
#define A_STRIDE 136
#define GEMM_SMEM (128 * A_STRIDE * 2 + 4096 * 8)   // 34816 + 32768 = 67584

__global__ __launch_bounds__(256, 3) void mma_gemm_kernel(
    const float* __restrict__ bias, float* __restrict__ out, int n_rows) {
    extern __shared__ char smem[];
    uint16_t* Asm = (uint16_t*)smem;                       // 34816 B
    uint2*    Wf  = (uint2*)(smem + 128 * A_STRIDE * 2);   // +32768 B

    int tid = threadIdx.x;
    int w = tid >> 5, lane = tid & 31;
    int g = lane >> 2, t = lane & 3;
    int wr = w & 3;        // row group (32 rows each)
    int wc = w >> 2;       // col half  (64 cols each)
    int row0 = blockIdx.x * 128;

    // ---- stage W fragments (32 KB) ----
    #pragma unroll
    for (int i = tid; i < 4096; i += 256) Wf[i] = g_wf[i];

    // ---- stage A: load fp32 agg, convert to fp16 in smem ----
    #pragma unroll
    for (int i = 0; i < 16; i++) {
        int idx4 = tid + i * 256;          // 0..4095
        int r  = idx4 >> 5;                // 0..127
        int c4 = idx4 & 31;                // 0..31
        float4 v = make_float4(0.f, 0.f, 0.f, 0.f);
        if (row0 + r < n_rows)
            v = *(const float4*)&g_agg[(size_t)(row0 + r) * D + c4 * 4];
        *(uint2*)&Asm[r * A_STRIDE + c4 * 4] =
            make_uint2(pack2(f2h(v.x), f2h(v.y)), pack2(f2h(v.z), f2h(v.w)));
    }
    __syncthreads();

    // ---- main mma loops ----
    float acc0[8][4], acc1[8][4];
    #pragma unroll
    for (int nt = 0; nt < 8; nt++)
        #pragma unroll
        for (int j = 0; j < 4; j++) { acc0[nt][j] = 0.f; acc1[nt][j] = 0.f; }

    int lrow = wr * 32 + (lane & 15);
    int lch  = (lane >> 4) & 1;

    for (int ks = 0; ks < 8; ks++) {
        uint32_t a0[4], a1[4];
        uint32_t adr0 = (uint32_t)__cvta_generic_to_shared(
            &Asm[lrow * A_STRIDE + ks * 16 + lch * 8]);
        uint32_t adr1 = (uint32_t)__cvta_generic_to_shared(
            &Asm[(lrow + 16) * A_STRIDE + ks * 16 + lch * 8]);
        LDSM_X4(a0, adr0);
        LDSM_X4(a1, adr1);
        #pragma unroll
        for (int nt = 0; nt < 8; nt++) {
            int ntg = wc * 8 + nt;
            uint2 b = Wf[(ks * 16 + ntg) * 32 + lane];
            MMA_F16(acc0[nt], a0, b.x, b.y);
            MMA_F16(acc1[nt], a1, b.x, b.y);
        }
    }

    // ---- epilogue: bias + relu + store (4 row frags per warp) ----
    int rbase = row0 + wr * 32 + g;
    #pragma unroll
    for (int nt = 0; nt < 8; nt++) {
        int col = wc * 64 + nt * 8 + 2 * t;
        float2 bv = *(const float2*)&bias[col];
        int r0 = rbase, r1 = rbase + 8, r2 = rbase + 16, r3 = rbase + 24;
        if (r0 < n_rows) {
            float2 o = make_float2(fmaxf(acc0[nt][0] + bv.x, 0.f),
                                   fmaxf(acc0[nt][1] + bv.y, 0.f));
            *(float2*)&out[(size_t)r0 * D + col] = o;
        }
        if (r1 < n_rows) {
            float2 o = make_float2(fmaxf(acc0[nt][2] + bv.x, 0.f),
                                   fmaxf(acc0[nt][3] + bv.y, 0.f));
            *(float2*)&out[(size_t)r1 * D + col] = o;
        }
        if (r2 < n_rows) {
            float2 o = make_float2(fmaxf(acc1[nt][0] + bv.x, 0.f),
                                   fmaxf(acc1[nt][1] + bv.y, 0.f));
            *(float2*)&out[(size_t)r2 * D + col] = o;
        }
        if (r3 < n_rows) {
            float2 o = make_float2(fmaxf(acc1[nt][2] + bv.x, 0.f),
                                   fmaxf(acc1[nt][3] + bv.y, 0.f));
            *(float2*)&out[(size_t)r3 * D + col] = o;
        }
    }
}

// ---------------------------------------------------------------
extern "C" void kernel_launch(void* const* d_in, const int* in_sizes, int n_in,
                              void* d_out, int out_size) {
    const float* x  = (const float*)d_in[0];   // [n_src, 128]
    const int*   ei = (const int*)d_in[1];     // [2, n_edge] int32
    const float* ew = (const float*)d_in[2];   // [n_edge]
    const float* Wm = (const float*)d_in[3];   // [128, 128]
    const float* b  = (const float*)d_in[4];   // [128]
    float* out = (float*)d_out;                // [n_out, 128]

    int n_src  = in_sizes[0] / D;
    int n_edge = in_sizes[2];
    int n_out  = out_size / D;
    int n_tot  = n_src + n_out;
    int nblk   = (n_out + SCAN_CHUNK - 1) / SCAN_CHUNK;

    cudaFuncSetAttribute(mma_gemm_kernel,
                         cudaFuncAttributeMaxDynamicSharedMemorySize, GEMM_SMEM);

    degcnt_kernel<<<(n_edge + 255) / 256, 256>>>(ei, ew, Wm, n_edge, n_tot, n_out);
    scanA_kernel<<<nblk, 1024>>>(n_out, nblk);
    scatter_kernel<<<(n_edge + 255) / 256, 256>>>(ei, ew, n_edge, n_tot, n_out);
    gather_kernel<<<(n_out + 7) / 8, 256>>>(x, n_out, n_tot);
    mma_gemm_kernel<<<(n_out + 127) / 128, 256, GEMM_SMEM>>>(b, out, n_out);
}

// round 16
// speedup vs baseline: 1.1991x; 1.0302x over previous
#include <cuda_runtime.h>
#include <cuda_fp16.h>
#include <cstdint>

#define D 128
#define MAX_N    150016
#define MAX_OUT  50048
#define MAX_E    500064   // padded +64: masked gather may read slots past E
#define SCAN_CHUNK 4096

// ---- device scratch (static zero-init; each replay re-zeroes what it dirtied
//      so every kernel_launch call sees the same initial state) ----
__device__ float  g_deg[MAX_N];          // zeroed by gather tail each run
__device__ int    g_cnt[MAX_OUT];        // zeroed by gather tail each run
__device__ int    g_off[MAX_OUT + 1];    // chunk-LOCAL exclusive offsets
__device__ int    g_cursor[MAX_OUT];     // chunk-LOCAL cursors
__device__ int    g_bsum[64];            // per-chunk totals
__device__ int    g_bpre[64];            // exclusive chunk prefix
__device__ int    g_done;                // scanA completion counter (self-resetting)
__device__ int2   g_epack[MAX_E];        // (row, coef) packed 8B
__device__ uint2  g_aggh[(size_t)MAX_OUT * 32];  // agg in fp16 (12.8 MB)
__device__ uint2  g_wf[8 * 16 * 32];     // W fp16 mma fragments [ks][nt][lane]

// ---- helpers ----
__device__ __forceinline__ uint16_t f2h(float f) {
    __half h = __float2half_rn(f);
    return *reinterpret_cast<uint16_t*>(&h);
}
__device__ __forceinline__ uint32_t pack2(uint16_t lo, uint16_t hi) {
    return (uint32_t)lo | ((uint32_t)hi << 16);
}

#define MMA_F16(ac, a, b0, b1)                                               \
    asm volatile(                                                            \
        "mma.sync.aligned.m16n8k16.row.col.f32.f16.f16.f32 "                 \
        "{%0,%1,%2,%3}, {%4,%5,%6,%7}, {%8,%9}, {%0,%1,%2,%3};"              \
        : "+f"((ac)[0]), "+f"((ac)[1]), "+f"((ac)[2]), "+f"((ac)[3])         \
        : "r"((a)[0]), "r"((a)[1]), "r"((a)[2]), "r"((a)[3]),                \
          "r"(b0), "r"(b1))

#define LDSM_X4(r, addr)                                                     \
    asm volatile(                                                            \
        "ldmatrix.sync.aligned.m8n8.x4.shared.b16 {%0,%1,%2,%3}, [%4];"      \
        : "=r"((r)[0]), "=r"((r)[1]), "=r"((r)[2]), "=r"((r)[3])             \
        : "r"(addr))

// ---------------------------------------------------------------
// W fragment prep (fp16, folded into degcnt_kernel)
// ---------------------------------------------------------------
__device__ __forceinline__ void wprep_one(const float* __restrict__ Wm, int idx) {
    int lane = idx & 31, nt = (idx >> 5) & 15, ks = idx >> 9;
    int g = lane >> 2, t = lane & 3;
    int n  = nt * 8 + g;
    int k0 = ks * 16 + 2 * t;
    uint16_t h00 = f2h(Wm[(k0 + 0) * D + n]);
    uint16_t h01 = f2h(Wm[(k0 + 1) * D + n]);
    uint16_t h10 = f2h(Wm[(k0 + 8) * D + n]);
    uint16_t h11 = f2h(Wm[(k0 + 9) * D + n]);
    g_wf[idx] = make_uint2(pack2(h00, h01), pack2(h10, h11));
}

// ---------------------------------------------------------------
// K1: degree accumulation (into ZEROED deg; self-loop +1 folded into
//     scatter's rsqrt(1+deg)) + dest histogram + W fragment prep.
// ---------------------------------------------------------------
__global__ void degcnt_kernel(const int* __restrict__ ei,
                              const float* __restrict__ ew,
                              const float* __restrict__ Wm, int n_edge,
                              int n_tot, int n_out) {
    int e = blockIdx.x * blockDim.x + threadIdx.x;
    if (e < 8 * 16 * 32) wprep_one(Wm, e);
    if (e >= n_edge) return;
    int row = ei[e];
    int col = ei[e + n_edge];
    if ((unsigned)row < (unsigned)n_tot) atomicAdd(&g_deg[row], ew[e]);
    if ((unsigned)col < (unsigned)n_out) atomicAdd(&g_cnt[col], 1);
}

// ---------------------------------------------------------------
// K2: per-chunk LOCAL exclusive scan + fused chunk-prefix
// ---------------------------------------------------------------
__global__ __launch_bounds__(1024) void scanA_kernel(int n, int nblk) {
    __shared__ int wsum[32];
    __shared__ int is_last;
    int t = threadIdx.x, lane = t & 31, wid = t >> 5;
    int base = blockIdx.x * SCAN_CHUNK + t * 4;
    int v0 = 0, v1 = 0, v2 = 0, v3 = 0;
    if (base + 3 < n) {
        int4 v = *(const int4*)&g_cnt[base];
        v0 = v.x; v1 = v.y; v2 = v.z; v3 = v.w;
    } else {
        if (base + 0 < n) v0 = g_cnt[base + 0];
        if (base + 1 < n) v1 = g_cnt[base + 1];
        if (base + 2 < n) v2 = g_cnt[base + 2];
        if (base + 3 < n) v3 = g_cnt[base + 3];
    }
    int tin = v0 + v1 + v2 + v3;
    int incl = tin;
    #pragma unroll
    for (int o = 1; o < 32; o <<= 1) {
        int s = __shfl_up_sync(0xffffffffu, incl, o);
        if (lane >= o) incl += s;
    }
    if (lane == 31) wsum[wid] = incl;
    __syncthreads();
    if (wid == 0) {
        int ws = wsum[lane];
        int winc = ws;
        #pragma unroll
        for (int o = 1; o < 32; o <<= 1) {
            int s = __shfl_up_sync(0xffffffffu, winc, o);
            if (lane >= o) winc += s;
        }
        wsum[lane] = winc - ws;
    }
    __syncthreads();
    int texcl = wsum[wid] + incl - tin;
    int e0 = texcl, e1 = e0 + v0, e2 = e1 + v1, e3 = e2 + v2;
    if (base + 0 < n) { g_off[base + 0] = e0; g_cursor[base + 0] = e0; }
    if (base + 1 < n) { g_off[base + 1] = e1; g_cursor[base + 1] = e1; }
    if (base + 2 < n) { g_off[base + 2] = e2; g_cursor[base + 2] = e2; }
    if (base + 3 < n) { g_off[base + 3] = e3; g_cursor[base + 3] = e3; }
    if (n >= base && n <= base + 3) {          // local sentinel at n
        int d = n - base;
        g_off[n] = (d == 0) ? e0 : (d == 1) ? e1 : (d == 2) ? e2 : e3;
    }
    if (t == 1023) g_bsum[blockIdx.x] = wsum[wid] + incl;   // chunk TOTAL

    // ---- fused chunk-prefix: last block to finish computes g_bpre ----
    __syncthreads();
    if (t == 0) {
        __threadfence();
        int old = atomicAdd(&g_done, 1);
        is_last = (old == nblk - 1);
    }
    __syncthreads();
    if (is_last && t < 32) {
        int v = (t < nblk) ? g_bsum[t] : 0;
        int ip = v;
        #pragma unroll
        for (int o = 1; o < 32; o <<= 1) {
            int s = __shfl_up_sync(0xffffffffu, ip, o);
            if (t >= o) ip += s;
        }
        if (t <= nblk) g_bpre[t] = ip - v;
        if (t == 0) {
            g_done = 0;                            // reset for next replay
            if ((n % SCAN_CHUNK) == 0) g_off[n] = 0;  // boundary sentinel
        }
    }
}

// ---------------------------------------------------------------
// K3: CSR placement (1 edge/thread), packed 8B store
// ---------------------------------------------------------------
__global__ void scatter_kernel(const int* __restrict__ ei,
                               const float* __restrict__ ew, int n_edge,
                               int n_tot, int n_out) {
    int e = blockIdx.x * blockDim.x + threadIdx.x;
    if (e >= n_edge) return;
    int row = ei[e];
    int col = ei[e + n_edge];
    if ((unsigned)row >= (unsigned)n_tot || (unsigned)col >= (unsigned)n_out)
        return;
    float c = ew[e] * rsqrtf(1.0f + g_deg[row]);
    int p = atomicAdd(&g_cursor[col], 1) + g_bpre[col >> 12];
    g_epack[p] = make_int2(row, __float_as_int(c));
}

// ---------------------------------------------------------------
// K4: warp-per-node gather (fp32 accumulate, masked 4-wide,
//     unroll 4 -> 16 x-row loads in flight) ; OUTPUT IN FP16
//     (identical math to R15: the agg->fp16 conversion that the mma
//      kernel used to do is moved here). Also re-zeroes scratch.
// ---------------------------------------------------------------
__global__ void gather_kernel(const float* __restrict__ x, int n_out, int n_tot) {
    int gtid = blockIdx.x * blockDim.x + threadIdx.x;
    if (gtid < n_tot) g_deg[gtid] = 0.0f;
    if (gtid < n_out) g_cnt[gtid] = 0;

    int w = gtid >> 5;
    int lane = threadIdx.x & 31;
    if (w >= n_out) return;
    int s = g_off[w]     + g_bpre[w >> 12];
    int e = g_off[w + 1] + g_bpre[(w + 1) >> 12];
    const float4* x4 = (const float4*)x;
    float4 acc = make_float4(0.f, 0.f, 0.f, 0.f);
    #pragma unroll 4
    for (int i = s; i < e; i += 4) {
        int2 p0 = g_epack[i];
        int2 p1 = g_epack[i + 1];
        int2 p2 = g_epack[i + 2];
        int2 p3 = g_epack[i + 3];
        float c0 = __int_as_float(p0.y);
        float c1 = (i + 1 < e) ? __int_as_float(p1.y) : 0.f;
        float c2 = (i + 2 < e) ? __int_as_float(p2.y) : 0.f;
        float c3 = (i + 3 < e) ? __int_as_float(p3.y) : 0.f;
        float4 v0 = x4[(size_t)p0.x * 32 + lane];
        float4 v1 = x4[(size_t)p1.x * 32 + lane];
        float4 v2 = x4[(size_t)p2.x * 32 + lane];
        float4 v3 = x4[(size_t)p3.x * 32 + lane];
        acc.x += c0 * v0.x + c1 * v1.x + c2 * v2.x + c3 * v3.x;
        acc.y += c0 * v0.y + c1 * v1.y + c2 * v2.y + c3 * v3.y;
        acc.z += c0 * v0.z + c1 * v1.z + c2 * v2.z + c3 * v3.z;
        acc.w += c0 * v0.w + c1 * v1.w + c2 * v2.w + c3 * v3.w;
    }
    // fp16 store: lane covers cols 4*lane .. 4*lane+3 (8B)
    g_aggh[(size_t)w * 32 + lane] =
        make_uint2(pack2(f2h(acc.x), f2h(acc.y)), pack2(f2h(acc.z), f2h(acc.w)));
}

// ---------------------------------------------------------------
// K5: tensor-core GEMM  out = relu(agg @ W + b), single fp16 MMA
//   tile = 128 rows x 128 cols, 8 warps: 4 row-groups (32 rows) x
//   2 col-halves (64 cols). A staged by direct uint2 copy (already
//   fp16). smem 66 KB -> 3 blocks/SM, grid 391 <= 444 single wave.
// ---------------------------------------------------------------
#define A_STRIDE 136
#define GEMM_SMEM (128 * A_STRIDE * 2 + 4096 * 8)   // 34816 + 32768 = 67584

__global__ __launch_bounds__(256, 3) void mma_gemm_kernel(
    const float* __restrict__ bias, float* __restrict__ out, int n_rows) {
    extern __shared__ char smem[];
    uint16_t* Asm = (uint16_t*)smem;                       // 34816 B
    uint2*    Wf  = (uint2*)(smem + 128 * A_STRIDE * 2);   // +32768 B

    int tid = threadIdx.x;
    int w = tid >> 5, lane = tid & 31;
    int g = lane >> 2, t = lane & 3;
    int wr = w & 3;        // row group (32 rows each)
    int wc = w >> 2;       // col half  (64 cols each)
    int row0 = blockIdx.x * 128;

    // ---- stage W fragments (32 KB) ----
    #pragma unroll
    for (int i = tid; i < 4096; i += 256) Wf[i] = g_wf[i];

    // ---- stage A: direct fp16 copy from g_aggh ----
    #pragma unroll
    for (int i = 0; i < 16; i++) {
        int idx4 = tid + i * 256;          // 0..4095
        int r  = idx4 >> 5;                // 0..127
        int c4 = idx4 & 31;                // 0..31
        uint2 v = make_uint2(0u, 0u);
        if (row0 + r < n_rows)
            v = g_aggh[(size_t)(row0 + r) * 32 + c4];
        *(uint2*)&Asm[r * A_STRIDE + c4 * 4] = v;
    }
    __syncthreads();

    // ---- main mma loops ----
    float acc0[8][4], acc1[8][4];
    #pragma unroll
    for (int nt = 0; nt < 8; nt++)
        #pragma unroll
        for (int j = 0; j < 4; j++) { acc0[nt][j] = 0.f; acc1[nt][j] = 0.f; }

    int lrow = wr * 32 + (lane & 15);
    int lch  = (lane >> 4) & 1;

    for (int ks = 0; ks < 8; ks++) {
        uint32_t a0[4], a1[4];
        uint32_t adr0 = (uint32_t)__cvta_generic_to_shared(
            &Asm[lrow * A_STRIDE + ks * 16 + lch * 8]);
        uint32_t adr1 = (uint32_t)__cvta_generic_to_shared(
            &Asm[(lrow + 16) * A_STRIDE + ks * 16 + lch * 8]);
        LDSM_X4(a0, adr0);
        LDSM_X4(a1, adr1);
        #pragma unroll
        for (int nt = 0; nt < 8; nt++) {
            int ntg = wc * 8 + nt;
            uint2 b = Wf[(ks * 16 + ntg) * 32 + lane];
            MMA_F16(acc0[nt], a0, b.x, b.y);
            MMA_F16(acc1[nt], a1, b.x, b.y);
        }
    }

    // ---- epilogue: bias + relu + store (4 row frags per warp) ----
    int rbase = row0 + wr * 32 + g;
    #pragma unroll
    for (int nt = 0; nt < 8; nt++) {
        int col = wc * 64 + nt * 8 + 2 * t;
        float2 bv = *(const float2*)&bias[col];
        int r0 = rbase, r1 = rbase + 8, r2 = rbase + 16, r3 = rbase + 24;
        if (r0 < n_rows) {
            float2 o = make_float2(fmaxf(acc0[nt][0] + bv.x, 0.f),
                                   fmaxf(acc0[nt][1] + bv.y, 0.f));
            *(float2*)&out[(size_t)r0 * D + col] = o;
        }
        if (r1 < n_rows) {
            float2 o = make_float2(fmaxf(acc0[nt][2] + bv.x, 0.f),
                                   fmaxf(acc0[nt][3] + bv.y, 0.f));
            *(float2*)&out[(size_t)r1 * D + col] = o;
        }
        if (r2 < n_rows) {
            float2 o = make_float2(fmaxf(acc1[nt][0] + bv.x, 0.f),
                                   fmaxf(acc1[nt][1] + bv.y, 0.f));
            *(float2*)&out[(size_t)r2 * D + col] = o;
        }
        if (r3 < n_rows) {
            float2 o = make_float2(fmaxf(acc1[nt][2] + bv.x, 0.f),
                                   fmaxf(acc1[nt][3] + bv.y, 0.f));
            *(float2*)&out[(size_t)r3 * D + col] = o;
        }
    }
}

// ---------------------------------------------------------------
extern "C" void kernel_launch(void* const* d_in, const int* in_sizes, int n_in,
                              void* d_out, int out_size) {
    const float* x  = (const float*)d_in[0];   // [n_src, 128]
    const int*   ei = (const int*)d_in[1];     // [2, n_edge] int32
    const float* ew = (const float*)d_in[2];   // [n_edge]
    const float* Wm = (const float*)d_in[3];   // [128, 128]
    const float* b  = (const float*)d_in[4];   // [128]
    float* out = (float*)d_out;                // [n_out, 128]

    int n_src  = in_sizes[0] / D;
    int n_edge = in_sizes[2];
    int n_out  = out_size / D;
    int n_tot  = n_src + n_out;
    int nblk   = (n_out + SCAN_CHUNK - 1) / SCAN_CHUNK;

    cudaFuncSetAttribute(mma_gemm_kernel,
                         cudaFuncAttributeMaxDynamicSharedMemorySize, GEMM_SMEM);

    degcnt_kernel<<<(n_edge + 255) / 256, 256>>>(ei, ew, Wm, n_edge, n_tot, n_out);
    scanA_kernel<<<nblk, 1024>>>(n_out, nblk);
    scatter_kernel<<<(n_edge + 255) / 256, 256>>>(ei, ew, n_edge, n_tot, n_out);
    gather_kernel<<<(n_out + 7) / 8, 256>>>(x, n_out, n_tot);
    mma_gemm_kernel<<<(n_out + 127) / 128, 256, GEMM_SMEM>>>(b, out, n_out);
}

// round 17
// speedup vs baseline: 1.2336x; 1.0287x over previous
#include <cuda_runtime.h>
#include <cuda_fp16.h>
#include <cstdint>

#define D 128
#define MAX_N    150016
#define MAX_OUT  50048
#define MAX_E    500064   // padded +64: masked gather may read slots past E
#define SCAN_CHUNK 4096

// ---- device scratch (static zero-init; each replay re-zeroes what it dirtied
//      so every kernel_launch call sees the same initial state) ----
__device__ float  g_deg[MAX_N];          // zeroed by gather tail each run
__device__ int    g_cnt[MAX_OUT];        // zeroed by gather tail each run
__device__ int    g_off[MAX_OUT + 1];    // chunk-LOCAL exclusive offsets
__device__ int    g_cursor[MAX_OUT];     // chunk-LOCAL cursors
__device__ int    g_bsum[64];            // per-chunk totals
__device__ int    g_bpre[64];            // exclusive chunk prefix
__device__ int    g_done;                // scanA completion counter (self-resetting)
__device__ int2   g_epack[MAX_E];        // (row, coef) packed 8B
__device__ uint2  g_aggh[(size_t)MAX_OUT * 32];  // agg in fp16 (12.8 MB)
__device__ uint2  g_wf[8 * 16 * 32];     // W fp16 mma fragments [ks][nt][lane]

// ---- helpers ----
__device__ __forceinline__ uint16_t f2h(float f) {
    __half h = __float2half_rn(f);
    return *reinterpret_cast<uint16_t*>(&h);
}
__device__ __forceinline__ uint32_t pack2(uint16_t lo, uint16_t hi) {
    return (uint32_t)lo | ((uint32_t)hi << 16);
}

#define MMA_F16(ac, a, b0, b1)                                               \
    asm volatile(                                                            \
        "mma.sync.aligned.m16n8k16.row.col.f32.f16.f16.f32 "                 \
        "{%0,%1,%2,%3}, {%4,%5,%6,%7}, {%8,%9}, {%0,%1,%2,%3};"              \
        : "+f"((ac)[0]), "+f"((ac)[1]), "+f"((ac)[2]), "+f"((ac)[3])         \
        : "r"((a)[0]), "r"((a)[1]), "r"((a)[2]), "r"((a)[3]),                \
          "r"(b0), "r"(b1))

#define LDSM_X4(r, addr)                                                     \
    asm volatile(                                                            \
        "ldmatrix.sync.aligned.m8n8.x4.shared.b16 {%0,%1,%2,%3}, [%4];"      \
        : "=r"((r)[0]), "=r"((r)[1]), "=r"((r)[2]), "=r"((r)[3])             \
        : "r"(addr))

// ---------------------------------------------------------------
// W fragment prep (fp16, folded into degcnt_kernel)
// ---------------------------------------------------------------
__device__ __forceinline__ void wprep_one(const float* __restrict__ Wm, int idx) {
    int lane = idx & 31, nt = (idx >> 5) & 15, ks = idx >> 9;
    int g = lane >> 2, t = lane & 3;
    int n  = nt * 8 + g;
    int k0 = ks * 16 + 2 * t;
    uint16_t h00 = f2h(Wm[(k0 + 0) * D + n]);
    uint16_t h01 = f2h(Wm[(k0 + 1) * D + n]);
    uint16_t h10 = f2h(Wm[(k0 + 8) * D + n]);
    uint16_t h11 = f2h(Wm[(k0 + 9) * D + n]);
    g_wf[idx] = make_uint2(pack2(h00, h01), pack2(h10, h11));
}

// ---------------------------------------------------------------
// K1: degree accumulation (into ZEROED deg; self-loop +1 folded into
//     scatter's rsqrt(1+deg)) + dest histogram + W fragment prep.
// ---------------------------------------------------------------
__global__ void degcnt_kernel(const int* __restrict__ ei,
                              const float* __restrict__ ew,
                              const float* __restrict__ Wm, int n_edge,
                              int n_tot, int n_out) {
    int e = blockIdx.x * blockDim.x + threadIdx.x;
    if (e < 8 * 16 * 32) wprep_one(Wm, e);
    if (e >= n_edge) return;
    int row = ei[e];
    int col = ei[e + n_edge];
    if ((unsigned)row < (unsigned)n_tot) atomicAdd(&g_deg[row], ew[e]);
    if ((unsigned)col < (unsigned)n_out) atomicAdd(&g_cnt[col], 1);
}

// ---------------------------------------------------------------
// K2: per-chunk LOCAL exclusive scan + fused chunk-prefix
// ---------------------------------------------------------------
__global__ __launch_bounds__(1024) void scanA_kernel(int n, int nblk) {
    __shared__ int wsum[32];
    __shared__ int is_last;
    int t = threadIdx.x, lane = t & 31, wid = t >> 5;
    int base = blockIdx.x * SCAN_CHUNK + t * 4;
    int v0 = 0, v1 = 0, v2 = 0, v3 = 0;
    if (base + 3 < n) {
        int4 v = *(const int4*)&g_cnt[base];
        v0 = v.x; v1 = v.y; v2 = v.z; v3 = v.w;
    } else {
        if (base + 0 < n) v0 = g_cnt[base + 0];
        if (base + 1 < n) v1 = g_cnt[base + 1];
        if (base + 2 < n) v2 = g_cnt[base + 2];
        if (base + 3 < n) v3 = g_cnt[base + 3];
    }
    int tin = v0 + v1 + v2 + v3;
    int incl = tin;
    #pragma unroll
    for (int o = 1; o < 32; o <<= 1) {
        int s = __shfl_up_sync(0xffffffffu, incl, o);
        if (lane >= o) incl += s;
    }
    if (lane == 31) wsum[wid] = incl;
    __syncthreads();
    if (wid == 0) {
        int ws = wsum[lane];
        int winc = ws;
        #pragma unroll
        for (int o = 1; o < 32; o <<= 1) {
            int s = __shfl_up_sync(0xffffffffu, winc, o);
            if (lane >= o) winc += s;
        }
        wsum[lane] = winc - ws;
    }
    __syncthreads();
    int texcl = wsum[wid] + incl - tin;
    int e0 = texcl, e1 = e0 + v0, e2 = e1 + v1, e3 = e2 + v2;
    if (base + 0 < n) { g_off[base + 0] = e0; g_cursor[base + 0] = e0; }
    if (base + 1 < n) { g_off[base + 1] = e1; g_cursor[base + 1] = e1; }
    if (base + 2 < n) { g_off[base + 2] = e2; g_cursor[base + 2] = e2; }
    if (base + 3 < n) { g_off[base + 3] = e3; g_cursor[base + 3] = e3; }
    if (n >= base && n <= base + 3) {          // local sentinel at n
        int d = n - base;
        g_off[n] = (d == 0) ? e0 : (d == 1) ? e1 : (d == 2) ? e2 : e3;
    }
    if (t == 1023) g_bsum[blockIdx.x] = wsum[wid] + incl;   // chunk TOTAL

    // ---- fused chunk-prefix: last block to finish computes g_bpre ----
    __syncthreads();
    if (t == 0) {
        __threadfence();
        int old = atomicAdd(&g_done, 1);
        is_last = (old == nblk - 1);
    }
    __syncthreads();
    if (is_last && t < 32) {
        int v = (t < nblk) ? g_bsum[t] : 0;
        int ip = v;
        #pragma unroll
        for (int o = 1; o < 32; o <<= 1) {
            int s = __shfl_up_sync(0xffffffffu, ip, o);
            if (t >= o) ip += s;
        }
        if (t <= nblk) g_bpre[t] = ip - v;
        if (t == 0) {
            g_done = 0;                            // reset for next replay
            if ((n % SCAN_CHUNK) == 0) g_off[n] = 0;  // boundary sentinel
        }
    }
}

// ---------------------------------------------------------------
// K3: CSR placement (1 edge/thread), packed 8B store
// ---------------------------------------------------------------
__global__ void scatter_kernel(const int* __restrict__ ei,
                               const float* __restrict__ ew, int n_edge,
                               int n_tot, int n_out) {
    int e = blockIdx.x * blockDim.x + threadIdx.x;
    if (e >= n_edge) return;
    int row = ei[e];
    int col = ei[e + n_edge];
    if ((unsigned)row >= (unsigned)n_tot || (unsigned)col >= (unsigned)n_out)
        return;
    float c = ew[e] * rsqrtf(1.0f + g_deg[row]);
    int p = atomicAdd(&g_cursor[col], 1) + g_bpre[col >> 12];
    g_epack[p] = make_int2(row, __float_as_int(c));
}

// ---------------------------------------------------------------
// K4: warp-per-node gather (fp32 accumulate, masked 4-wide,
//     unroll 2 — R15-proven loop shape) ; OUTPUT IN FP16.
//     Also re-zeroes scratch for the next replay.
// ---------------------------------------------------------------
__global__ void gather_kernel(const float* __restrict__ x, int n_out, int n_tot) {
    int gtid = blockIdx.x * blockDim.x + threadIdx.x;
    if (gtid < n_tot) g_deg[gtid] = 0.0f;
    if (gtid < n_out) g_cnt[gtid] = 0;

    int w = gtid >> 5;
    int lane = threadIdx.x & 31;
    if (w >= n_out) return;
    int s = g_off[w]     + g_bpre[w >> 12];
    int e = g_off[w + 1] + g_bpre[(w + 1) >> 12];
    const float4* x4 = (const float4*)x;
    float4 acc = make_float4(0.f, 0.f, 0.f, 0.f);
    #pragma unroll 2
    for (int i = s; i < e; i += 4) {
        int2 p0 = g_epack[i];
        int2 p1 = g_epack[i + 1];
        int2 p2 = g_epack[i + 2];
        int2 p3 = g_epack[i + 3];
        float c0 = __int_as_float(p0.y);
        float c1 = (i + 1 < e) ? __int_as_float(p1.y) : 0.f;
        float c2 = (i + 2 < e) ? __int_as_float(p2.y) : 0.f;
        float c3 = (i + 3 < e) ? __int_as_float(p3.y) : 0.f;
        float4 v0 = x4[(size_t)p0.x * 32 + lane];
        float4 v1 = x4[(size_t)p1.x * 32 + lane];
        float4 v2 = x4[(size_t)p2.x * 32 + lane];
        float4 v3 = x4[(size_t)p3.x * 32 + lane];
        acc.x += c0 * v0.x + c1 * v1.x + c2 * v2.x + c3 * v3.x;
        acc.y += c0 * v0.y + c1 * v1.y + c2 * v2.y + c3 * v3.y;
        acc.z += c0 * v0.z + c1 * v1.z + c2 * v2.z + c3 * v3.z;
        acc.w += c0 * v0.w + c1 * v1.w + c2 * v2.w + c3 * v3.w;
    }
    // fp16 store: lane covers cols 4*lane .. 4*lane+3 (8B)
    g_aggh[(size_t)w * 32 + lane] =
        make_uint2(pack2(f2h(acc.x), f2h(acc.y)), pack2(f2h(acc.z), f2h(acc.w)));
}

// ---------------------------------------------------------------
// K5: tensor-core GEMM  out = relu(agg @ W + b), single fp16 MMA
//   tile = 128 rows x 128 cols, 8 warps: 4 row-groups (32 rows) x
//   2 col-halves (64 cols). A staged by direct uint2 copy (already
//   fp16). smem 66 KB -> 3 blocks/SM, grid 391 <= 444 single wave.
// ---------------------------------------------------------------
#define A_STRIDE 136
#define GEMM_SMEM (128 * A_STRIDE * 2 + 4096 * 8)   // 34816 + 32768 = 67584

__global__ __launch_bounds__(256, 3) void mma_gemm_kernel(
    const float* __restrict__ bias, float* __restrict__ out, int n_rows) {
    extern __shared__ char smem[];
    uint16_t* Asm = (uint16_t*)smem;                       // 34816 B
    uint2*    Wf  = (uint2*)(smem + 128 * A_STRIDE * 2);   // +32768 B

    int tid = threadIdx.x;
    int w = tid >> 5, lane = tid & 31;
    int g = lane >> 2, t = lane & 3;
    int wr = w & 3;        // row group (32 rows each)
    int wc = w >> 2;       // col half  (64 cols each)
    int row0 = blockIdx.x * 128;

    // ---- stage W fragments (32 KB) ----
    #pragma unroll
    for (int i = tid; i < 4096; i += 256) Wf[i] = g_wf[i];

    // ---- stage A: direct fp16 copy from g_aggh ----
    #pragma unroll
    for (int i = 0; i < 16; i++) {
        int idx4 = tid + i * 256;          // 0..4095
        int r  = idx4 >> 5;                // 0..127
        int c4 = idx4 & 31;                // 0..31
        uint2 v = make_uint2(0u, 0u);
        if (row0 + r < n_rows)
            v = g_aggh[(size_t)(row0 + r) * 32 + c4];
        *(uint2*)&Asm[r * A_STRIDE + c4 * 4] = v;
    }
    __syncthreads();

    // ---- main mma loops ----
    float acc0[8][4], acc1[8][4];
    #pragma unroll
    for (int nt = 0; nt < 8; nt++)
        #pragma unroll
        for (int j = 0; j < 4; j++) { acc0[nt][j] = 0.f; acc1[nt][j] = 0.f; }

    int lrow = wr * 32 + (lane & 15);
    int lch  = (lane >> 4) & 1;

    for (int ks = 0; ks < 8; ks++) {
        uint32_t a0[4], a1[4];
        uint32_t adr0 = (uint32_t)__cvta_generic_to_shared(
            &Asm[lrow * A_STRIDE + ks * 16 + lch * 8]);
        uint32_t adr1 = (uint32_t)__cvta_generic_to_shared(
            &Asm[(lrow + 16) * A_STRIDE + ks * 16 + lch * 8]);
        LDSM_X4(a0, adr0);
        LDSM_X4(a1, adr1);
        #pragma unroll
        for (int nt = 0; nt < 8; nt++) {
            int ntg = wc * 8 + nt;
            uint2 b = Wf[(ks * 16 + ntg) * 32 + lane];
            MMA_F16(acc0[nt], a0, b.x, b.y);
            MMA_F16(acc1[nt], a1, b.x, b.y);
        }
    }

    // ---- epilogue: bias + relu + store (4 row frags per warp) ----
    int rbase = row0 + wr * 32 + g;
    #pragma unroll
    for (int nt = 0; nt < 8; nt++) {
        int col = wc * 64 + nt * 8 + 2 * t;
        float2 bv = *(const float2*)&bias[col];
        int r0 = rbase, r1 = rbase + 8, r2 = rbase + 16, r3 = rbase + 24;
        if (r0 < n_rows) {
            float2 o = make_float2(fmaxf(acc0[nt][0] + bv.x, 0.f),
                                   fmaxf(acc0[nt][1] + bv.y, 0.f));
            *(float2*)&out[(size_t)r0 * D + col] = o;
        }
        if (r1 < n_rows) {
            float2 o = make_float2(fmaxf(acc0[nt][2] + bv.x, 0.f),
                                   fmaxf(acc0[nt][3] + bv.y, 0.f));
            *(float2*)&out[(size_t)r1 * D + col] = o;
        }
        if (r2 < n_rows) {
            float2 o = make_float2(fmaxf(acc1[nt][0] + bv.x, 0.f),
                                   fmaxf(acc1[nt][1] + bv.y, 0.f));
            *(float2*)&out[(size_t)r2 * D + col] = o;
        }
        if (r3 < n_rows) {
            float2 o = make_float2(fmaxf(acc1[nt][2] + bv.x, 0.f),
                                   fmaxf(acc1[nt][3] + bv.y, 0.f));
            *(float2*)&out[(size_t)r3 * D + col] = o;
        }
    }
}

// ---------------------------------------------------------------
extern "C" void kernel_launch(void* const* d_in, const int* in_sizes, int n_in,
                              void* d_out, int out_size) {
    const float* x  = (const float*)d_in[0];   // [n_src, 128]
    const int*   ei = (const int*)d_in[1];     // [2, n_edge] int32
    const float* ew = (const float*)d_in[2];   // [n_edge]
    const float* Wm = (const float*)d_in[3];   // [128, 128]
    const float* b  = (const float*)d_in[4];   // [128]
    float* out = (float*)d_out;                // [n_out, 128]

    int n_src  = in_sizes[0] / D;
    int n_edge = in_sizes[2];
    int n_out  = out_size / D;
    int n_tot  = n_src + n_out;
    int nblk   = (n_out + SCAN_CHUNK - 1) / SCAN_CHUNK;

    cudaFuncSetAttribute(mma_gemm_kernel,
                         cudaFuncAttributeMaxDynamicSharedMemorySize, GEMM_SMEM);

    degcnt_kernel<<<(n_edge + 255) / 256, 256>>>(ei, ew, Wm, n_edge, n_tot, n_out);
    scanA_kernel<<<nblk, 1024>>>(n_out, nblk);
    scatter_kernel<<<(n_edge + 255) / 256, 256>>>(ei, ew, n_edge, n_tot, n_out);
    gather_kernel<<<(n_out + 7) / 8, 256>>>(x, n_out, n_tot);
    mma_gemm_kernel<<<(n_out + 127) / 128, 256, GEMM_SMEM>>>(b, out, n_out);
}